// round 5
// baseline (speedup 1.0000x reference)
#include <cuda_runtime.h>
#include <cuda_bf16.h>
#include <math.h>
#include <stdint.h>

#define T_SEQ 2048
#define N_EMBD 2048
#define N_HEAD 16
#define N_GROUPS 4
#define HEAD 128
#define QKV_DIM 3072
#define INTER 5632
#define VOCAB 32000

// ---------------- scratch (device globals; no runtime allocation) ----------------
__device__ float g_x[T_SEQ * N_EMBD];
__device__ float g_n[T_SEQ * N_EMBD];
__device__ float g_qkv[T_SEQ * QKV_DIM];
__device__ float g_q[N_HEAD * T_SEQ * HEAD];
__device__ float g_k[N_GROUPS * T_SEQ * HEAD];
__device__ float g_v[N_GROUPS * T_SEQ * HEAD];
__device__ float g_y[T_SEQ * N_EMBD];
__device__ float g_h1[T_SEQ * INTER];
__device__ float g_h2[T_SEQ * INTER];

// ---------------- embedding gather ----------------
__global__ void k_embed(const int* __restrict__ idx, const float* __restrict__ wte,
                        float* __restrict__ x) {
    int t = blockIdx.x;
    int row = idx[t];
    const float4* src = (const float4*)(wte + (size_t)row * N_EMBD);
    float4* dst = (float4*)(x + (size_t)t * N_EMBD);
    for (int i = threadIdx.x; i < N_EMBD / 4; i += blockDim.x) dst[i] = src[i];
}

// ---------------- rmsnorm (one block per row) ----------------
__global__ void k_rmsnorm(const float* __restrict__ x, const float* __restrict__ w,
                          float* __restrict__ o) {
    int t = blockIdx.x;
    const float4* xr = (const float4*)(x + (size_t)t * N_EMBD);
    const float4* wr = (const float4*)w;
    float4* orow = (float4*)(o + (size_t)t * N_EMBD);
    float ss = 0.f;
    for (int i = threadIdx.x; i < N_EMBD / 4; i += blockDim.x) {
        float4 v = xr[i];
        ss += v.x * v.x + v.y * v.y + v.z * v.z + v.w * v.w;
    }
    __shared__ float red[32];
    for (int o2 = 16; o2; o2 >>= 1) ss += __shfl_xor_sync(0xffffffffu, ss, o2);
    int warp = threadIdx.x >> 5, lane = threadIdx.x & 31;
    if (lane == 0) red[warp] = ss;
    __syncthreads();
    if (warp == 0) {
        float v = (lane < (int)(blockDim.x >> 5)) ? red[lane] : 0.f;
        for (int o2 = 16; o2; o2 >>= 1) v += __shfl_xor_sync(0xffffffffu, v, o2);
        if (lane == 0) red[0] = v;
    }
    __syncthreads();
    float r = rsqrtf(red[0] / (float)N_EMBD + 1e-5f);
    for (int i = threadIdx.x; i < N_EMBD / 4; i += blockDim.x) {
        float4 v = xr[i];
        float4 wv = wr[i];
        v.x *= r * wv.x; v.y *= r * wv.y; v.z *= r * wv.z; v.w *= r * wv.w;
        orow[i] = v;
    }
}

// ---------------- tensor-core GEMM (split-bf16): C = A[M,K] @ B[N,K]^T (+res) ----
// 128x128x32 tiles, 256 threads = 8 warps (4 x-M, 2 x-N), warp tile 32x64.
// fp32 operands split into bf16 hi+lo; acc += ah*bh + ah*bl + al*bh (fp32 accum).
// Register-staged prefetch: next K-tile's LDGs issue before the MMA phase.

#define LDS_K 40  // 32 bf16 + 8 pad -> 80B rows, conflict-free ldmatrix

__device__ __forceinline__ void ldsm4(uint32_t* r, uint32_t addr) {
    asm volatile("ldmatrix.sync.aligned.m8n8.x4.shared.b16 {%0,%1,%2,%3}, [%4];"
                 : "=r"(r[0]), "=r"(r[1]), "=r"(r[2]), "=r"(r[3]) : "r"(addr));
}

__device__ __forceinline__ void mma16816(float* d, const uint32_t* a,
                                         uint32_t b0, uint32_t b1) {
    asm volatile(
        "mma.sync.aligned.m16n8k16.row.col.f32.bf16.bf16.f32 "
        "{%0,%1,%2,%3}, {%4,%5,%6,%7}, {%8,%9}, {%0,%1,%2,%3};"
        : "+f"(d[0]), "+f"(d[1]), "+f"(d[2]), "+f"(d[3])
        : "r"(a[0]), "r"(a[1]), "r"(a[2]), "r"(a[3]), "r"(b0), "r"(b1));
}

__device__ __forceinline__ void split_pair(float x, float y, uint32_t& hi, uint32_t& lo) {
    __nv_bfloat16 hx = __float2bfloat16(x);
    __nv_bfloat16 hy = __float2bfloat16(y);
    __nv_bfloat16 lx = __float2bfloat16(x - __bfloat162float(hx));
    __nv_bfloat16 ly = __float2bfloat16(y - __bfloat162float(hy));
    hi = ((uint32_t)__bfloat16_as_ushort(hy) << 16) | (uint32_t)__bfloat16_as_ushort(hx);
    lo = ((uint32_t)__bfloat16_as_ushort(ly) << 16) | (uint32_t)__bfloat16_as_ushort(lx);
}

__global__ __launch_bounds__(256) void k_gemm_tc(const float* __restrict__ A,
                                                 const float* __restrict__ B,
                                                 const float* __restrict__ res,
                                                 float* __restrict__ C,
                                                 int M, int N, int K) {
    __shared__ __nv_bfloat16 Ah[128][LDS_K], Al[128][LDS_K];
    __shared__ __nv_bfloat16 Bh[128][LDS_K], Bl[128][LDS_K];
    int tid = threadIdx.x, lane = tid & 31, wid = tid >> 5;
    int wm = (wid & 3) * 32, wn = (wid >> 2) * 64;
    int bm = blockIdx.y * 128, bn = blockIdx.x * 128;
    const float* Ab = A + (size_t)bm * K;
    const float* Bb = B + (size_t)bn * K;

    uint32_t ah_base = (uint32_t)__cvta_generic_to_shared(Ah);
    uint32_t al_base = (uint32_t)__cvta_generic_to_shared(Al);
    uint32_t bh_base = (uint32_t)__cvta_generic_to_shared(Bh);
    uint32_t bl_base = (uint32_t)__cvta_generic_to_shared(Bl);

    // per-thread load coordinates (row r, col c within 128x32 tile)
    int lrow = tid >> 3;            // 0..31 step over 128 rows in 4 chunks of 32
    int lcol = (tid & 7) * 4;       // 0..28

    // ldmatrix lane-address components (canonical m16n8k16 mappings)
    int arow = (lane & 7) + ((lane >> 3) & 1) * 8;
    int acol = (lane >> 4) * 8;
    int brow = (lane & 7) + ((lane >> 4) & 1) * 8;
    int bcol = ((lane >> 3) & 1) * 8;

    float acc[2][8][4];
#pragma unroll
    for (int i = 0; i < 2; i++)
#pragma unroll
        for (int j = 0; j < 8; j++)
#pragma unroll
            for (int q = 0; q < 4; q++) acc[i][j][q] = 0.f;

    float4 ra[4], rb[4];
    // prologue: stage tile k0=0 into registers
#pragma unroll
    for (int i = 0; i < 4; i++) {
        int r = lrow + i * 32;
        ra[i] = *(const float4*)&Ab[(size_t)r * K + lcol];
        rb[i] = *(const float4*)&Bb[(size_t)r * K + lcol];
    }

    for (int k0 = 0; k0 < K; k0 += 32) {
        // split staged registers to bf16 hi/lo in smem
#pragma unroll
        for (int i = 0; i < 4; i++) {
            int r = lrow + i * 32, c = lcol;
            uint32_t h0, l0, h1, l1;
            split_pair(ra[i].x, ra[i].y, h0, l0);
            split_pair(ra[i].z, ra[i].w, h1, l1);
            *(uint32_t*)&Ah[r][c] = h0; *(uint32_t*)&Ah[r][c + 2] = h1;
            *(uint32_t*)&Al[r][c] = l0; *(uint32_t*)&Al[r][c + 2] = l1;
            split_pair(rb[i].x, rb[i].y, h0, l0);
            split_pair(rb[i].z, rb[i].w, h1, l1);
            *(uint32_t*)&Bh[r][c] = h0; *(uint32_t*)&Bh[r][c + 2] = h1;
            *(uint32_t*)&Bl[r][c] = l0; *(uint32_t*)&Bl[r][c + 2] = l1;
        }
        __syncthreads();
        // issue next tile's global loads (latency hidden under MMA phase)
        if (k0 + 32 < K) {
            int kn = k0 + 32;
#pragma unroll
            for (int i = 0; i < 4; i++) {
                int r = lrow + i * 32;
                ra[i] = *(const float4*)&Ab[(size_t)r * K + kn + lcol];
                rb[i] = *(const float4*)&Bb[(size_t)r * K + kn + lcol];
            }
        }
#pragma unroll
        for (int ks = 0; ks < 32; ks += 16) {
            uint32_t afh[2][4], afl[2][4];
#pragma unroll
            for (int mi = 0; mi < 2; mi++) {
                uint32_t off = (uint32_t)(((wm + mi * 16 + arow) * LDS_K + ks + acol) * 2);
                ldsm4(afh[mi], ah_base + off);
                ldsm4(afl[mi], al_base + off);
            }
#pragma unroll
            for (int nj = 0; nj < 4; nj++) {
                uint32_t off = (uint32_t)(((wn + nj * 16 + brow) * LDS_K + ks + bcol) * 2);
                uint32_t bfh[4], bfl[4];
                ldsm4(bfh, bh_base + off);
                ldsm4(bfl, bl_base + off);
#pragma unroll
                for (int mi = 0; mi < 2; mi++) {
                    float* d0 = acc[mi][nj * 2];
                    float* d1 = acc[mi][nj * 2 + 1];
                    mma16816(d0, afh[mi], bfh[0], bfh[1]);
                    mma16816(d0, afh[mi], bfl[0], bfl[1]);
                    mma16816(d0, afl[mi], bfh[0], bfh[1]);
                    mma16816(d1, afh[mi], bfh[2], bfh[3]);
                    mma16816(d1, afh[mi], bfl[2], bfl[3]);
                    mma16816(d1, afl[mi], bfh[2], bfh[3]);
                }
            }
        }
        __syncthreads();
    }
    // epilogue: d frag rows lane>>2 (+8), cols (lane&3)*2 (+1)
#pragma unroll
    for (int mi = 0; mi < 2; mi++) {
#pragma unroll
        for (int ni = 0; ni < 8; ni++) {
            int m0 = bm + wm + mi * 16 + (lane >> 2);
            int n0 = bn + wn + ni * 8 + (lane & 3) * 2;
            size_t o0 = (size_t)m0 * N + n0;
            size_t o1 = (size_t)(m0 + 8) * N + n0;
            float2 u = make_float2(acc[mi][ni][0], acc[mi][ni][1]);
            float2 w = make_float2(acc[mi][ni][2], acc[mi][ni][3]);
            if (res) {
                float2 r0 = *(const float2*)&res[o0];
                float2 r1 = *(const float2*)&res[o1];
                u.x += r0.x; u.y += r0.y; w.x += r1.x; w.y += r1.y;
            }
            *(float2*)&C[o0] = u;
            *(float2*)&C[o1] = w;
        }
    }
}

// ---------------- rope + elu+1 (+ scale folded into q); split qkv ----------------
__global__ void k_rope(const float* __restrict__ qkv, float* __restrict__ Qp,
                       float* __restrict__ Kp, float* __restrict__ Vp) {
    int t = blockIdx.x;
    const float* src = qkv + (size_t)t * QKV_DIM;
    const float scale = 0.08838834764831845f;  // 1/sqrt(128)
    for (int it = threadIdx.x; it < 1024; it += blockDim.x) {
        int hh = it >> 6, p = it & 63;
        int gg = hh >> 2, j = hh & 3;
        const float* s = src + gg * 768 + j * 128;
        float x1 = s[p], x2 = s[p + 64];
        double theta = pow(10000.0, -(double)p / 64.0);
        double ang = (double)t * theta;
        float c = (float)cos(ang), sn = (float)sin(ang);
        float r1 = x1 * c - x2 * sn;
        float r2 = x1 * sn + x2 * c;
        r1 = (r1 > 0.f) ? (r1 + 1.f) : expf(r1);
        r2 = (r2 > 0.f) ? (r2 + 1.f) : expf(r2);
        float* dst = Qp + ((size_t)hh * T_SEQ + t) * HEAD;
        dst[p] = r1 * scale;
        dst[p + 64] = r2 * scale;
    }
    for (int it = threadIdx.x; it < 256; it += blockDim.x) {
        int gg = it >> 6, p = it & 63;
        const float* s = src + gg * 768 + 512;
        float x1 = s[p], x2 = s[p + 64];
        double theta = pow(10000.0, -(double)p / 64.0);
        double ang = (double)t * theta;
        float c = (float)cos(ang), sn = (float)sin(ang);
        float r1 = x1 * c - x2 * sn;
        float r2 = x1 * sn + x2 * c;
        r1 = (r1 > 0.f) ? (r1 + 1.f) : expf(r1);
        r2 = (r2 > 0.f) ? (r2 + 1.f) : expf(r2);
        float* dst = Kp + ((size_t)gg * T_SEQ + t) * HEAD;
        dst[p] = r1;
        dst[p + 64] = r2;
    }
    for (int it = threadIdx.x; it < 512; it += blockDim.x) {
        int gg = it >> 7, d = it & 127;
        Vp[((size_t)gg * T_SEQ + t) * HEAD + d] = src[gg * 768 + 640 + d];
    }
}

// ---------------- masked linear-normalized attention ----------------
#define AT_BQ 64
#define AT_BS 32
#define ATTN_SMEM ((64 * 132 + 32 * 132 + 32 * 132 + 64 * 33 + 64) * 4)

__global__ __launch_bounds__(256, 2) void k_attn(const float* __restrict__ Q,
                                                 const float* __restrict__ K,
                                                 const float* __restrict__ V,
                                                 float* __restrict__ Y) {
    extern __shared__ float sm[];
    float* qs = sm;
    float* ks = qs + 64 * 132;
    float* vs = ks + 32 * 132;
    float* sc = vs + 32 * 132;
    float* denS = sc + 64 * 33;
    int h = blockIdx.y, qt = blockIdx.x;
    int g = h >> 2;
    int tid = threadIdx.x;
    const float* qb = Q + ((size_t)h * T_SEQ + (size_t)qt * AT_BQ) * HEAD;
    const float* kb = K + (size_t)g * T_SEQ * HEAD;
    const float* vb = V + (size_t)g * T_SEQ * HEAD;
#pragma unroll
    for (int i = 0; i < 8; i++) {
        int li = tid + i * 256;
        int r = li >> 5, c = (li & 31) * 4;
        *(float4*)(qs + r * 132 + c) = *(const float4*)(qb + (size_t)r * HEAD + c);
    }
    float acc[8][4] = {};
    float den = 0.f;
    int dg = (tid & 31) * 4;
    int qg = (tid >> 5) * 8;
    int qq = tid >> 2;
    int sbase = tid & 3;
    int tq = qt * AT_BQ + qq;
    int qend = (qt + 1) * AT_BQ;
    for (int s0 = 0; s0 < qend; s0 += AT_BS) {
        __syncthreads();
#pragma unroll
        for (int i = 0; i < 4; i++) {
            int li = tid + i * 256;
            int r = li >> 5, c = (li & 31) * 4;
            *(float4*)(ks + r * 132 + c) = *(const float4*)(kb + (size_t)(s0 + r) * HEAD + c);
            *(float4*)(vs + r * 132 + c) = *(const float4*)(vb + (size_t)(s0 + r) * HEAD + c);
        }
        __syncthreads();
        float ds[8] = {0.f, 0.f, 0.f, 0.f, 0.f, 0.f, 0.f, 0.f};
        const float4* qp = (const float4*)(qs + qq * 132);
#pragma unroll 4
        for (int kk = 0; kk < 32; kk++) {
            float4 qv = qp[kk];
#pragma unroll
            for (int j = 0; j < 8; j++) {
                float4 kv = ((const float4*)(ks + (sbase + 4 * j) * 132))[kk];
                ds[j] += qv.x * kv.x + qv.y * kv.y + qv.z * kv.z + qv.w * kv.w;
            }
        }
#pragma unroll
        for (int j = 0; j < 8; j++) {
            int ss = sbase + 4 * j;
            sc[qq * 33 + ss] = (s0 + ss <= tq) ? ds[j] : 0.f;
        }
        __syncthreads();
        if (tid < 64) {
            float d2 = 0.f;
#pragma unroll
            for (int ss = 0; ss < 32; ss++) d2 += sc[tid * 33 + ss];
            den += d2;
        }
#pragma unroll 4
        for (int ss = 0; ss < 32; ss++) {
            float4 vv = *(const float4*)(vs + ss * 132 + dg);
#pragma unroll
            for (int i = 0; i < 8; i++) {
                float s = sc[(qg + i) * 33 + ss];
                acc[i][0] += s * vv.x; acc[i][1] += s * vv.y;
                acc[i][2] += s * vv.z; acc[i][3] += s * vv.w;
            }
        }
    }
    __syncthreads();
    if (tid < 64) denS[tid] = den;
    __syncthreads();
#pragma unroll
    for (int i = 0; i < 8; i++) {
        float inv = 1.0f / (denS[qg + i] + 1e-8f);
        float4 v;
        v.x = acc[i][0] * inv; v.y = acc[i][1] * inv;
        v.z = acc[i][2] * inv; v.w = acc[i][3] * inv;
        int trow = qt * AT_BQ + qg + i;
        *(float4*)&Y[(size_t)trow * N_EMBD + h * HEAD + dg] = v;
    }
}

// ---------------- silu(h1)*h2 -> h1 ----------------
__global__ void k_silu(float* __restrict__ h1, const float* __restrict__ h2, int n4) {
    int i = blockIdx.x * blockDim.x + threadIdx.x;
    if (i < n4) {
        float4 a = ((float4*)h1)[i];
        float4 b = ((const float4*)h2)[i];
        a.x = a.x / (1.f + expf(-a.x)) * b.x;
        a.y = a.y / (1.f + expf(-a.y)) * b.y;
        a.z = a.z / (1.f + expf(-a.z)) * b.z;
        a.w = a.w / (1.f + expf(-a.w)) * b.w;
        ((float4*)h1)[i] = a;
    }
}

// ---------------- driver ----------------
extern "C" void kernel_launch(void* const* d_in, const int* in_sizes, int n_in,
                              void* d_out, int out_size) {
    const int* idx = (const int*)d_in[0];
    const float* wte = (const float*)d_in[1];
    const float* attn_w = (const float*)d_in[2];
    const float* proj_w = (const float*)d_in[3];
    const float* w1 = (const float*)d_in[4];
    const float* w2 = (const float*)d_in[5];
    const float* w3 = (const float*)d_in[6];
    const float* norm1 = (const float*)d_in[7];
    const float* norm2 = (const float*)d_in[8];
    const float* lnf = (const float*)d_in[9];
    const float* lmh = (const float*)d_in[10];
    float* out = (float*)d_out;

    float *x, *n, *qkv, *q, *k, *v, *y, *h1, *h2;
    cudaGetSymbolAddress((void**)&x, g_x);
    cudaGetSymbolAddress((void**)&n, g_n);
    cudaGetSymbolAddress((void**)&qkv, g_qkv);
    cudaGetSymbolAddress((void**)&q, g_q);
    cudaGetSymbolAddress((void**)&k, g_k);
    cudaGetSymbolAddress((void**)&v, g_v);
    cudaGetSymbolAddress((void**)&y, g_y);
    cudaGetSymbolAddress((void**)&h1, g_h1);
    cudaGetSymbolAddress((void**)&h2, g_h2);

    cudaFuncSetAttribute(k_attn, cudaFuncAttributeMaxDynamicSharedMemorySize, ATTN_SMEM);

    k_embed<<<T_SEQ, 256>>>(idx, wte, x);

    for (int l = 0; l < 2; l++) {
        k_rmsnorm<<<T_SEQ, 256>>>(x, norm1 + (size_t)l * N_EMBD, n);
        k_gemm_tc<<<dim3(QKV_DIM / 128, T_SEQ / 128), 256>>>(
            n, attn_w + (size_t)l * QKV_DIM * N_EMBD, nullptr, qkv,
            T_SEQ, QKV_DIM, N_EMBD);
        k_rope<<<T_SEQ, 256>>>(qkv, q, k, v);
        k_attn<<<dim3(T_SEQ / AT_BQ, N_HEAD), 256, ATTN_SMEM>>>(q, k, v, y);
        k_gemm_tc<<<dim3(N_EMBD / 128, T_SEQ / 128), 256>>>(
            y, proj_w + (size_t)l * N_EMBD * N_EMBD, x, x,
            T_SEQ, N_EMBD, N_EMBD);
        k_rmsnorm<<<T_SEQ, 256>>>(x, norm2 + (size_t)l * N_EMBD, n);
        k_gemm_tc<<<dim3(INTER / 128, T_SEQ / 128), 256>>>(
            n, w1 + (size_t)l * INTER * N_EMBD, nullptr, h1,
            T_SEQ, INTER, N_EMBD);
        k_gemm_tc<<<dim3(INTER / 128, T_SEQ / 128), 256>>>(
            n, w2 + (size_t)l * INTER * N_EMBD, nullptr, h2,
            T_SEQ, INTER, N_EMBD);
        k_silu<<<(T_SEQ * INTER / 4 + 255) / 256, 256>>>(h1, h2, T_SEQ * INTER / 4);
        k_gemm_tc<<<dim3(N_EMBD / 128, T_SEQ / 128), 256>>>(
            h1, w3 + (size_t)l * N_EMBD * INTER, x, x,
            T_SEQ, N_EMBD, INTER);
    }

    k_rmsnorm<<<T_SEQ, 256>>>(x, lnf, n);
    k_gemm_tc<<<dim3(VOCAB / 128, T_SEQ / 128), 256>>>(
        n, lmh, nullptr, out, T_SEQ, VOCAB, N_EMBD);
}

// round 8
// speedup vs baseline: 1.2988x; 1.2988x over previous
#include <cuda_runtime.h>
#include <cuda_bf16.h>
#include <math.h>
#include <stdint.h>

#define T_SEQ 2048
#define N_EMBD 2048
#define N_HEAD 16
#define N_GROUPS 4
#define HEAD 128
#define QKV_DIM 3072
#define INTER 5632
#define VOCAB 32000

// ---------------- scratch (device globals; no runtime allocation) ----------------
__device__ float g_x[T_SEQ * N_EMBD];
__device__ float g_n[T_SEQ * N_EMBD];
__device__ float g_qkv[T_SEQ * QKV_DIM];
__device__ float g_q[N_HEAD * T_SEQ * HEAD];
__device__ float g_k[N_GROUPS * T_SEQ * HEAD];
__device__ float g_v[N_GROUPS * T_SEQ * HEAD];
__device__ float g_y[T_SEQ * N_EMBD];
__device__ float g_h1[T_SEQ * INTER];
__device__ float g_h2[T_SEQ * INTER];

// ---------------- embedding gather ----------------
__global__ void k_embed(const int* __restrict__ idx, const float* __restrict__ wte,
                        float* __restrict__ x) {
    int t = blockIdx.x;
    int row = idx[t];
    const float4* src = (const float4*)(wte + (size_t)row * N_EMBD);
    float4* dst = (float4*)(x + (size_t)t * N_EMBD);
    for (int i = threadIdx.x; i < N_EMBD / 4; i += blockDim.x) dst[i] = src[i];
}

// ---------------- rmsnorm (one block per row) ----------------
__global__ void k_rmsnorm(const float* __restrict__ x, const float* __restrict__ w,
                          float* __restrict__ o) {
    int t = blockIdx.x;
    const float4* xr = (const float4*)(x + (size_t)t * N_EMBD);
    const float4* wr = (const float4*)w;
    float4* orow = (float4*)(o + (size_t)t * N_EMBD);
    float ss = 0.f;
    for (int i = threadIdx.x; i < N_EMBD / 4; i += blockDim.x) {
        float4 v = xr[i];
        ss += v.x * v.x + v.y * v.y + v.z * v.z + v.w * v.w;
    }
    __shared__ float red[32];
    for (int o2 = 16; o2; o2 >>= 1) ss += __shfl_xor_sync(0xffffffffu, ss, o2);
    int warp = threadIdx.x >> 5, lane = threadIdx.x & 31;
    if (lane == 0) red[warp] = ss;
    __syncthreads();
    if (warp == 0) {
        float v = (lane < (int)(blockDim.x >> 5)) ? red[lane] : 0.f;
        for (int o2 = 16; o2; o2 >>= 1) v += __shfl_xor_sync(0xffffffffu, v, o2);
        if (lane == 0) red[0] = v;
    }
    __syncthreads();
    float r = rsqrtf(red[0] / (float)N_EMBD + 1e-5f);
    for (int i = threadIdx.x; i < N_EMBD / 4; i += blockDim.x) {
        float4 v = xr[i];
        float4 wv = wr[i];
        v.x *= r * wv.x; v.y *= r * wv.y; v.z *= r * wv.z; v.w *= r * wv.w;
        orow[i] = v;
    }
}

// ---------------- tensor-core GEMM (split-bf16): C = A[M,K] @ B[N,K]^T (+res) ----
// 128x128x32 tiles, 256 threads = 8 warps (4 x-M, 2 x-N), warp tile 32x64.
// fp32 operands split into bf16 hi+lo; acc += ah*bh + ah*bl + al*bh (fp32 accum).
// Double-buffered smem stages: STS(i+1) and LDG(i+2) overlap MMA(i); one sync/iter.

#define LDS_K 40                 // 32 bf16 + 8 pad -> 80B rows, conflict-free ldmatrix
#define TILE_ELEMS (128 * LDS_K) // per matrix per stage
#define STG_ELEMS (4 * TILE_ELEMS)
#define GEMM_SMEM (2 * STG_ELEMS * 2)  // bytes (bf16)

__device__ __forceinline__ void ldsm4(uint32_t* r, uint32_t addr) {
    asm volatile("ldmatrix.sync.aligned.m8n8.x4.shared.b16 {%0,%1,%2,%3}, [%4];"
                 : "=r"(r[0]), "=r"(r[1]), "=r"(r[2]), "=r"(r[3]) : "r"(addr));
}

__device__ __forceinline__ void mma16816(float* d, const uint32_t* a,
                                         uint32_t b0, uint32_t b1) {
    asm volatile(
        "mma.sync.aligned.m16n8k16.row.col.f32.bf16.bf16.f32 "
        "{%0,%1,%2,%3}, {%4,%5,%6,%7}, {%8,%9}, {%0,%1,%2,%3};"
        : "+f"(d[0]), "+f"(d[1]), "+f"(d[2]), "+f"(d[3])
        : "r"(a[0]), "r"(a[1]), "r"(a[2]), "r"(a[3]), "r"(b0), "r"(b1));
}

__device__ __forceinline__ void split_pair(float x, float y, uint32_t& hi, uint32_t& lo) {
    __nv_bfloat16 hx = __float2bfloat16(x);
    __nv_bfloat16 hy = __float2bfloat16(y);
    __nv_bfloat16 lx = __float2bfloat16(x - __bfloat162float(hx));
    __nv_bfloat16 ly = __float2bfloat16(y - __bfloat162float(hy));
    hi = ((uint32_t)__bfloat16_as_ushort(hy) << 16) | (uint32_t)__bfloat16_as_ushort(hx);
    lo = ((uint32_t)__bfloat16_as_ushort(ly) << 16) | (uint32_t)__bfloat16_as_ushort(lx);
}

__global__ __launch_bounds__(256) void k_gemm_tc(const float* __restrict__ A,
                                                 const float* __restrict__ B,
                                                 const float* __restrict__ res,
                                                 float* __restrict__ C,
                                                 int M, int N, int K) {
    extern __shared__ __nv_bfloat16 sm_[];
    // stage s layout (elements): Ah @ s*STG, Al @ +TILE, Bh @ +2*TILE, Bl @ +3*TILE
    int tid = threadIdx.x, lane = tid & 31, wid = tid >> 5;
    int wm = (wid & 3) * 32, wn = (wid >> 2) * 64;
    int bm = blockIdx.y * 128, bn = blockIdx.x * 128;
    const float* Ab = A + (size_t)bm * K;
    const float* Bb = B + (size_t)bn * K;

    uint32_t sbase = (uint32_t)__cvta_generic_to_shared(sm_);

    int lrow = tid >> 3;        // 0..31 (4 chunks of 32 rows)
    int lcol = (tid & 7) * 4;   // 0..28

    // ldmatrix lane-address components (canonical m16n8k16 mappings)
    int arow = (lane & 7) + ((lane >> 3) & 1) * 8;
    int acol = (lane >> 4) * 8;
    int brow = (lane & 7) + ((lane >> 4) & 1) * 8;
    int bcol = ((lane >> 3) & 1) * 8;

    float acc[2][8][4];
#pragma unroll
    for (int i = 0; i < 2; i++)
#pragma unroll
        for (int j = 0; j < 8; j++)
#pragma unroll
            for (int q = 0; q < 4; q++) acc[i][j][q] = 0.f;

    float4 ra[4], rb[4];

    // --- prologue: tile0 -> smem stage 0; stage regs with tile1 ---
#pragma unroll
    for (int i = 0; i < 4; i++) {
        int r = lrow + i * 32;
        ra[i] = *(const float4*)&Ab[(size_t)r * K + lcol];
        rb[i] = *(const float4*)&Bb[(size_t)r * K + lcol];
    }
#pragma unroll
    for (int i = 0; i < 4; i++) {
        int r = lrow + i * 32;
        uint32_t h0, l0, h1, l1;
        split_pair(ra[i].x, ra[i].y, h0, l0);
        split_pair(ra[i].z, ra[i].w, h1, l1);
        *(uint32_t*)&sm_[r * LDS_K + lcol] = h0;
        *(uint32_t*)&sm_[r * LDS_K + lcol + 2] = h1;
        *(uint32_t*)&sm_[TILE_ELEMS + r * LDS_K + lcol] = l0;
        *(uint32_t*)&sm_[TILE_ELEMS + r * LDS_K + lcol + 2] = l1;
        split_pair(rb[i].x, rb[i].y, h0, l0);
        split_pair(rb[i].z, rb[i].w, h1, l1);
        *(uint32_t*)&sm_[2 * TILE_ELEMS + r * LDS_K + lcol] = h0;
        *(uint32_t*)&sm_[2 * TILE_ELEMS + r * LDS_K + lcol + 2] = h1;
        *(uint32_t*)&sm_[3 * TILE_ELEMS + r * LDS_K + lcol] = l0;
        *(uint32_t*)&sm_[3 * TILE_ELEMS + r * LDS_K + lcol + 2] = l1;
    }
    if (K > 32) {
#pragma unroll
        for (int i = 0; i < 4; i++) {
            int r = lrow + i * 32;
            ra[i] = *(const float4*)&Ab[(size_t)r * K + 32 + lcol];
            rb[i] = *(const float4*)&Bb[(size_t)r * K + 32 + lcol];
        }
    }
    __syncthreads();

    for (int k0 = 0; k0 < K; k0 += 32) {
        int cur = (k0 >> 5) & 1, nxt = cur ^ 1;
        // STS tile k0+32 (staged in regs) into the other stage
        if (k0 + 32 < K) {
            int nb = nxt * STG_ELEMS;
#pragma unroll
            for (int i = 0; i < 4; i++) {
                int r = lrow + i * 32;
                uint32_t h0, l0, h1, l1;
                split_pair(ra[i].x, ra[i].y, h0, l0);
                split_pair(ra[i].z, ra[i].w, h1, l1);
                *(uint32_t*)&sm_[nb + r * LDS_K + lcol] = h0;
                *(uint32_t*)&sm_[nb + r * LDS_K + lcol + 2] = h1;
                *(uint32_t*)&sm_[nb + TILE_ELEMS + r * LDS_K + lcol] = l0;
                *(uint32_t*)&sm_[nb + TILE_ELEMS + r * LDS_K + lcol + 2] = l1;
                split_pair(rb[i].x, rb[i].y, h0, l0);
                split_pair(rb[i].z, rb[i].w, h1, l1);
                *(uint32_t*)&sm_[nb + 2 * TILE_ELEMS + r * LDS_K + lcol] = h0;
                *(uint32_t*)&sm_[nb + 2 * TILE_ELEMS + r * LDS_K + lcol + 2] = h1;
                *(uint32_t*)&sm_[nb + 3 * TILE_ELEMS + r * LDS_K + lcol] = l0;
                *(uint32_t*)&sm_[nb + 3 * TILE_ELEMS + r * LDS_K + lcol + 2] = l1;
            }
        }
        // LDG tile k0+64 into regs (hidden under MMA + next STS)
        if (k0 + 64 < K) {
            int kn = k0 + 64;
#pragma unroll
            for (int i = 0; i < 4; i++) {
                int r = lrow + i * 32;
                ra[i] = *(const float4*)&Ab[(size_t)r * K + kn + lcol];
                rb[i] = *(const float4*)&Bb[(size_t)r * K + kn + lcol];
            }
        }
        // MMA from stage cur
        uint32_t ah_b = sbase + (uint32_t)(cur * STG_ELEMS) * 2;
        uint32_t al_b = ah_b + TILE_ELEMS * 2;
        uint32_t bh_b = ah_b + 2 * TILE_ELEMS * 2;
        uint32_t bl_b = ah_b + 3 * TILE_ELEMS * 2;
#pragma unroll
        for (int ks = 0; ks < 32; ks += 16) {
            uint32_t afh[2][4], afl[2][4];
#pragma unroll
            for (int mi = 0; mi < 2; mi++) {
                uint32_t off = (uint32_t)(((wm + mi * 16 + arow) * LDS_K + ks + acol) * 2);
                ldsm4(afh[mi], ah_b + off);
                ldsm4(afl[mi], al_b + off);
            }
#pragma unroll
            for (int nj = 0; nj < 4; nj++) {
                uint32_t off = (uint32_t)(((wn + nj * 16 + brow) * LDS_K + ks + bcol) * 2);
                uint32_t bfh[4], bfl[4];
                ldsm4(bfh, bh_b + off);
                ldsm4(bfl, bl_b + off);
#pragma unroll
                for (int mi = 0; mi < 2; mi++) {
                    float* d0 = acc[mi][nj * 2];
                    float* d1 = acc[mi][nj * 2 + 1];
                    mma16816(d0, afh[mi], bfh[0], bfh[1]);
                    mma16816(d0, afh[mi], bfl[0], bfl[1]);
                    mma16816(d0, afl[mi], bfh[0], bfh[1]);
                    mma16816(d1, afh[mi], bfh[2], bfh[3]);
                    mma16816(d1, afh[mi], bfl[2], bfl[3]);
                    mma16816(d1, afl[mi], bfh[2], bfh[3]);
                }
            }
        }
        __syncthreads();
    }
    // epilogue: d frag rows lane>>2 (+8), cols (lane&3)*2 (+1)
#pragma unroll
    for (int mi = 0; mi < 2; mi++) {
#pragma unroll
        for (int ni = 0; ni < 8; ni++) {
            int m0 = bm + wm + mi * 16 + (lane >> 2);
            int n0 = bn + wn + ni * 8 + (lane & 3) * 2;
            size_t o0 = (size_t)m0 * N + n0;
            size_t o1 = (size_t)(m0 + 8) * N + n0;
            float2 u = make_float2(acc[mi][ni][0], acc[mi][ni][1]);
            float2 w = make_float2(acc[mi][ni][2], acc[mi][ni][3]);
            if (res) {
                float2 r0 = *(const float2*)&res[o0];
                float2 r1 = *(const float2*)&res[o1];
                u.x += r0.x; u.y += r0.y; w.x += r1.x; w.y += r1.y;
            }
            *(float2*)&C[o0] = u;
            *(float2*)&C[o1] = w;
        }
    }
}

// ---------------- rope + elu+1 (+ scale folded into q); split qkv ----------------
// fp32 trig (matches reference, which computes angles/cos in fp32)
#define ROPE_C1 (-0.2076205059375f)  // -log2(10000)/64

__global__ void k_rope(const float* __restrict__ qkv, float* __restrict__ Qp,
                       float* __restrict__ Kp, float* __restrict__ Vp) {
    int t = blockIdx.x;
    const float* src = qkv + (size_t)t * QKV_DIM;
    const float scale = 0.08838834764831845f;  // 1/sqrt(128)
    for (int it = threadIdx.x; it < 1024; it += blockDim.x) {
        int hh = it >> 6, p = it & 63;
        int gg = hh >> 2, j = hh & 3;
        const float* s = src + gg * 768 + j * 128;
        float x1 = s[p], x2 = s[p + 64];
        float theta = exp2f((float)p * ROPE_C1);
        float c, sn;
        sincosf((float)t * theta, &sn, &c);
        float r1 = x1 * c - x2 * sn;
        float r2 = x1 * sn + x2 * c;
        r1 = (r1 > 0.f) ? (r1 + 1.f) : expf(r1);
        r2 = (r2 > 0.f) ? (r2 + 1.f) : expf(r2);
        float* dst = Qp + ((size_t)hh * T_SEQ + t) * HEAD;
        dst[p] = r1 * scale;
        dst[p + 64] = r2 * scale;
    }
    for (int it = threadIdx.x; it < 256; it += blockDim.x) {
        int gg = it >> 6, p = it & 63;
        const float* s = src + gg * 768 + 512;
        float x1 = s[p], x2 = s[p + 64];
        float theta = exp2f((float)p * ROPE_C1);
        float c, sn;
        sincosf((float)t * theta, &sn, &c);
        float r1 = x1 * c - x2 * sn;
        float r2 = x1 * sn + x2 * c;
        r1 = (r1 > 0.f) ? (r1 + 1.f) : expf(r1);
        r2 = (r2 > 0.f) ? (r2 + 1.f) : expf(r2);
        float* dst = Kp + ((size_t)gg * T_SEQ + t) * HEAD;
        dst[p] = r1;
        dst[p + 64] = r2;
    }
    for (int it = threadIdx.x; it < 512; it += blockDim.x) {
        int gg = it >> 7, d = it & 127;
        Vp[((size_t)gg * T_SEQ + t) * HEAD + d] = src[gg * 768 + 640 + d];
    }
}

// ---------------- masked linear-normalized attention ----------------
#define AT_BQ 64
#define AT_BS 32
#define ATTN_SMEM ((64 * 132 + 32 * 132 + 32 * 132 + 64 * 33 + 64) * 4)

__global__ __launch_bounds__(256, 2) void k_attn(const float* __restrict__ Q,
                                                 const float* __restrict__ K,
                                                 const float* __restrict__ V,
                                                 float* __restrict__ Y) {
    extern __shared__ float sm[];
    float* qs = sm;
    float* ks = qs + 64 * 132;
    float* vs = ks + 32 * 132;
    float* sc = vs + 32 * 132;
    float* denS = sc + 64 * 33;
    int h = blockIdx.y, qt = blockIdx.x;
    int g = h >> 2;
    int tid = threadIdx.x;
    const float* qb = Q + ((size_t)h * T_SEQ + (size_t)qt * AT_BQ) * HEAD;
    const float* kb = K + (size_t)g * T_SEQ * HEAD;
    const float* vb = V + (size_t)g * T_SEQ * HEAD;
#pragma unroll
    for (int i = 0; i < 8; i++) {
        int li = tid + i * 256;
        int r = li >> 5, c = (li & 31) * 4;
        *(float4*)(qs + r * 132 + c) = *(const float4*)(qb + (size_t)r * HEAD + c);
    }
    float acc[8][4] = {};
    float den = 0.f;
    int dg = (tid & 31) * 4;
    int qg = (tid >> 5) * 8;
    int qq = tid >> 2;
    int sbase = tid & 3;
    int tq = qt * AT_BQ + qq;
    int qend = (qt + 1) * AT_BQ;
    for (int s0 = 0; s0 < qend; s0 += AT_BS) {
        __syncthreads();
#pragma unroll
        for (int i = 0; i < 4; i++) {
            int li = tid + i * 256;
            int r = li >> 5, c = (li & 31) * 4;
            *(float4*)(ks + r * 132 + c) = *(const float4*)(kb + (size_t)(s0 + r) * HEAD + c);
            *(float4*)(vs + r * 132 + c) = *(const float4*)(vb + (size_t)(s0 + r) * HEAD + c);
        }
        __syncthreads();
        float ds[8] = {0.f, 0.f, 0.f, 0.f, 0.f, 0.f, 0.f, 0.f};
        const float4* qp = (const float4*)(qs + qq * 132);
#pragma unroll 4
        for (int kk = 0; kk < 32; kk++) {
            float4 qv = qp[kk];
#pragma unroll
            for (int j = 0; j < 8; j++) {
                float4 kv = ((const float4*)(ks + (sbase + 4 * j) * 132))[kk];
                ds[j] += qv.x * kv.x + qv.y * kv.y + qv.z * kv.z + qv.w * kv.w;
            }
        }
#pragma unroll
        for (int j = 0; j < 8; j++) {
            int ss = sbase + 4 * j;
            sc[qq * 33 + ss] = (s0 + ss <= tq) ? ds[j] : 0.f;
        }
        __syncthreads();
        if (tid < 64) {
            float d2 = 0.f;
#pragma unroll
            for (int ss = 0; ss < 32; ss++) d2 += sc[tid * 33 + ss];
            den += d2;
        }
#pragma unroll 4
        for (int ss = 0; ss < 32; ss++) {
            float4 vv = *(const float4*)(vs + ss * 132 + dg);
#pragma unroll
            for (int i = 0; i < 8; i++) {
                float s = sc[(qg + i) * 33 + ss];
                acc[i][0] += s * vv.x; acc[i][1] += s * vv.y;
                acc[i][2] += s * vv.z; acc[i][3] += s * vv.w;
            }
        }
    }
    __syncthreads();
    if (tid < 64) denS[tid] = den;
    __syncthreads();
#pragma unroll
    for (int i = 0; i < 8; i++) {
        float inv = 1.0f / (denS[qg + i] + 1e-8f);
        float4 v;
        v.x = acc[i][0] * inv; v.y = acc[i][1] * inv;
        v.z = acc[i][2] * inv; v.w = acc[i][3] * inv;
        int trow = qt * AT_BQ + qg + i;
        *(float4*)&Y[(size_t)trow * N_EMBD + h * HEAD + dg] = v;
    }
}

// ---------------- silu(h1)*h2 -> h1 ----------------
__global__ void k_silu(float* __restrict__ h1, const float* __restrict__ h2, int n4) {
    int i = blockIdx.x * blockDim.x + threadIdx.x;
    if (i < n4) {
        float4 a = ((float4*)h1)[i];
        float4 b = ((const float4*)h2)[i];
        a.x = a.x / (1.f + expf(-a.x)) * b.x;
        a.y = a.y / (1.f + expf(-a.y)) * b.y;
        a.z = a.z / (1.f + expf(-a.z)) * b.z;
        a.w = a.w / (1.f + expf(-a.w)) * b.w;
        ((float4*)h1)[i] = a;
    }
}

// ---------------- driver ----------------
extern "C" void kernel_launch(void* const* d_in, const int* in_sizes, int n_in,
                              void* d_out, int out_size) {
    const int* idx = (const int*)d_in[0];
    const float* wte = (const float*)d_in[1];
    const float* attn_w = (const float*)d_in[2];
    const float* proj_w = (const float*)d_in[3];
    const float* w1 = (const float*)d_in[4];
    const float* w2 = (const float*)d_in[5];
    const float* w3 = (const float*)d_in[6];
    const float* norm1 = (const float*)d_in[7];
    const float* norm2 = (const float*)d_in[8];
    const float* lnf = (const float*)d_in[9];
    const float* lmh = (const float*)d_in[10];
    float* out = (float*)d_out;

    float *x, *n, *qkv, *q, *k, *v, *y, *h1, *h2;
    cudaGetSymbolAddress((void**)&x, g_x);
    cudaGetSymbolAddress((void**)&n, g_n);
    cudaGetSymbolAddress((void**)&qkv, g_qkv);
    cudaGetSymbolAddress((void**)&q, g_q);
    cudaGetSymbolAddress((void**)&k, g_k);
    cudaGetSymbolAddress((void**)&v, g_v);
    cudaGetSymbolAddress((void**)&y, g_y);
    cudaGetSymbolAddress((void**)&h1, g_h1);
    cudaGetSymbolAddress((void**)&h2, g_h2);

    cudaFuncSetAttribute(k_attn, cudaFuncAttributeMaxDynamicSharedMemorySize, ATTN_SMEM);
    cudaFuncSetAttribute(k_gemm_tc, cudaFuncAttributeMaxDynamicSharedMemorySize, GEMM_SMEM);

    k_embed<<<T_SEQ, 256>>>(idx, wte, x);

    for (int l = 0; l < 2; l++) {
        k_rmsnorm<<<T_SEQ, 256>>>(x, norm1 + (size_t)l * N_EMBD, n);
        k_gemm_tc<<<dim3(QKV_DIM / 128, T_SEQ / 128), 256, GEMM_SMEM>>>(
            n, attn_w + (size_t)l * QKV_DIM * N_EMBD, nullptr, qkv,
            T_SEQ, QKV_DIM, N_EMBD);
        k_rope<<<T_SEQ, 256>>>(qkv, q, k, v);
        k_attn<<<dim3(T_SEQ / AT_BQ, N_HEAD), 256, ATTN_SMEM>>>(q, k, v, y);
        k_gemm_tc<<<dim3(N_EMBD / 128, T_SEQ / 128), 256, GEMM_SMEM>>>(
            y, proj_w + (size_t)l * N_EMBD * N_EMBD, x, x,
            T_SEQ, N_EMBD, N_EMBD);
        k_rmsnorm<<<T_SEQ, 256>>>(x, norm2 + (size_t)l * N_EMBD, n);
        k_gemm_tc<<<dim3(INTER / 128, T_SEQ / 128), 256, GEMM_SMEM>>>(
            n, w1 + (size_t)l * INTER * N_EMBD, nullptr, h1,
            T_SEQ, INTER, N_EMBD);
        k_gemm_tc<<<dim3(INTER / 128, T_SEQ / 128), 256, GEMM_SMEM>>>(
            n, w2 + (size_t)l * INTER * N_EMBD, nullptr, h2,
            T_SEQ, INTER, N_EMBD);
        k_silu<<<(T_SEQ * INTER / 4 + 255) / 256, 256>>>(h1, h2, T_SEQ * INTER / 4);
        k_gemm_tc<<<dim3(N_EMBD / 128, T_SEQ / 128), 256, GEMM_SMEM>>>(
            h1, w3 + (size_t)l * N_EMBD * INTER, x, x,
            T_SEQ, N_EMBD, INTER);
    }

    k_rmsnorm<<<T_SEQ, 256>>>(x, lnf, n);
    k_gemm_tc<<<dim3(VOCAB / 128, T_SEQ / 128), 256, GEMM_SMEM>>>(
        n, lmh, nullptr, out, T_SEQ, VOCAB, N_EMBD);
}